// round 6
// baseline (speedup 1.0000x reference)
#include <cuda_runtime.h>

// Problem shape (fixed by the dataset): feature1/feature2 are (8, 256, 512, 512) fp32, NCHW.
#define NB 8
#define NC 256
#define HWD 512
#define POOLK 16
#define PH (HWD / POOLK)   // 32 pooled rows
#define PW (HWD / POOLK)   // 32 pooled cols
// samples per channel for the statistics: B * PH * PW
#define NSAMP (NB * PH * PW)   // 8192

// Per-channel accumulators: [c*5 + {0:sx, 1:sy, 2:sxx, 3:syy, 4:sxy}]
__device__ double g_acc[NC * 5];

__global__ void zero_acc_kernel() {
    int i = blockIdx.x * blockDim.x + threadIdx.x;
    if (i < NC * 5) g_acc[i] = 0.0;
}

// One block per (b, c, ph) strip: 16 input rows x 512 cols of each feature.
// 256 threads: lane l owns pooled column l (cols [16l, 16l+16)),
// warp w (0..7) owns input rows {2w, 2w+1} within the strip.
__global__ __launch_bounds__(256) void pool_stats_kernel(
    const float* __restrict__ f1, const float* __restrict__ f2)
{
    const int bid = blockIdx.x;
    const int ph  = bid & (PH - 1);          // 5 bits
    const int c   = (bid >> 5) & (NC - 1);   // 8 bits
    const int b   = bid >> 13;

    const int t = threadIdx.x;
    const int w = t >> 5;   // warp 0..7
    const int l = t & 31;   // lane = pooled column

    // Base element offset of this thread's first row segment
    const long long row0 = (long long)(b * NC + c) * HWD + (long long)ph * POOLK + 2 * w;
    const long long base = row0 * HWD + (long long)l * POOLK;

    const float4* p1 = (const float4*)(f1 + base);
    const float4* p2 = (const float4*)(f2 + base);

    float s1 = 0.f, s2 = 0.f;
#pragma unroll
    for (int r = 0; r < 2; r++) {
#pragma unroll
        for (int k = 0; k < 4; k++) {
            float4 v = p1[r * (HWD / 4) + k];
            s1 += (v.x + v.y) + (v.z + v.w);
            float4 u = p2[r * (HWD / 4) + k];
            s2 += (u.x + u.y) + (u.z + u.w);
        }
    }

    __shared__ float sm1[8][32];
    __shared__ float sm2[8][32];
    sm1[w][l] = s1;
    sm2[w][l] = s2;
    __syncthreads();

    if (w == 0) {
        float xs = 0.f, ys = 0.f;
#pragma unroll
        for (int i = 0; i < 8; i++) { xs += sm1[i][l]; ys += sm2[i][l]; }
        // pooled values for (b, c, ph, pw=l)
        const float x = xs * (1.0f / (POOLK * POOLK));
        const float y = ys * (1.0f / (POOLK * POOLK));

        float a1 = x, a2 = y, a11 = x * x, a22 = y * y, a12 = x * y;
#pragma unroll
        for (int off = 16; off > 0; off >>= 1) {
            a1  += __shfl_down_sync(0xffffffffu, a1,  off);
            a2  += __shfl_down_sync(0xffffffffu, a2,  off);
            a11 += __shfl_down_sync(0xffffffffu, a11, off);
            a22 += __shfl_down_sync(0xffffffffu, a22, off);
            a12 += __shfl_down_sync(0xffffffffu, a12, off);
        }
        if (l == 0) {
            atomicAdd(&g_acc[c * 5 + 0], (double)a1);
            atomicAdd(&g_acc[c * 5 + 1], (double)a2);
            atomicAdd(&g_acc[c * 5 + 2], (double)a11);
            atomicAdd(&g_acc[c * 5 + 3], (double)a22);
            atomicAdd(&g_acc[c * 5 + 4], (double)a12);
        }
    }
}

__global__ __launch_bounds__(NC) void finalize_kernel(float* out) {
    const int c = threadIdx.x;
    const double n = (double)NSAMP;

    const double s1  = g_acc[c * 5 + 0];
    const double s2  = g_acc[c * 5 + 1];
    const double s11 = g_acc[c * 5 + 2];
    const double s22 = g_acc[c * 5 + 3];
    const double s12 = g_acc[c * 5 + 4];

    const double m1 = s1 / n;
    const double m2 = s2 / n;
    // biased covariance (torch.mean of products of deviations)
    const double cov = s12 / n - m1 * m2;
    // unbiased std (torch.std, ddof = 1)
    const double v1 = (s11 - s1 * s1 / n) / (n - 1.0);
    const double v2 = (s22 - s2 * s2 / n) / (n - 1.0);
    const double corr = cov / (sqrt(v1) * sqrt(v2) + 1e-8);

    __shared__ double sm[NC];
    sm[c] = fabs(corr);
    __syncthreads();
    for (int s = NC / 2; s > 0; s >>= 1) {
        if (c < s) sm[c] += sm[c + s];
        __syncthreads();
    }
    if (c == 0) out[0] = (float)(1.0 - sm[0] / (double)NC);
}

extern "C" void kernel_launch(void* const* d_in, const int* in_sizes, int n_in,
                              void* d_out, int out_size) {
    const float* f1 = (const float*)d_in[0];
    const float* f2 = (const float*)d_in[1];
    float* out = (float*)d_out;

    zero_acc_kernel<<<(NC * 5 + 255) / 256, 256>>>();
    pool_stats_kernel<<<NB * NC * PH, 256>>>(f1, f2);
    finalize_kernel<<<1, NC>>>(out);
}

// round 9
// speedup vs baseline: 1.0064x; 1.0064x over previous
#include <cuda_runtime.h>

// Problem shape (fixed by the dataset): feature1/feature2 are (8, 256, 512, 512) fp32, NCHW.
#define NB 8
#define NC 256
#define HWD 512
#define POOLK 16
#define PH (HWD / POOLK)   // 32 pooled rows
#define PW (HWD / POOLK)   // 32 pooled cols
#define NSAMP (NB * PH * PW)   // 8192 samples per channel

// Per-channel accumulators: [c*5 + {0:sx, 1:sy, 2:sxx, 3:syy, 4:sxy}]
// Statically zero-initialized; finalize_kernel restores them to zero after
// reading, so every kernel_launch (and every graph replay) sees zeros.
__device__ double g_acc[NC * 5];

// One block per (b, c, ph) strip: 16 input rows x 512 cols of each feature.
// 256 threads = 8 warps; warp w owns input rows {2w, 2w+1} of the strip.
// Loads are fully warp-coalesced: lane l reads float4 at column 4*(32*i + l),
// i = 0..3, so each LDG.128 covers 4 full 128B lines.
// Pooled column of (i, l) is i*8 + l/4; 4-lane shuffle groups reduce to it.
__global__ __launch_bounds__(256) void pool_stats_kernel(
    const float* __restrict__ f1, const float* __restrict__ f2)
{
    const int bid = blockIdx.x;
    const int ph  = bid & (PH - 1);          // 5 bits
    const int c   = (bid >> 5) & (NC - 1);   // 8 bits
    const int b   = bid >> 13;

    const int t = threadIdx.x;
    const int w = t >> 5;   // warp 0..7
    const int l = t & 31;   // lane

    // First of the two rows this warp owns
    const long long row0 = ((long long)(b * NC + c) * HWD + (long long)ph * POOLK + 2 * w);
    const float4* p1 = (const float4*)(f1 + row0 * HWD) + l;
    const float4* p2 = (const float4*)(f2 + row0 * HWD) + l;

    float part1[4] = {0.f, 0.f, 0.f, 0.f};
    float part2[4] = {0.f, 0.f, 0.f, 0.f};
#pragma unroll
    for (int r = 0; r < 2; r++) {
        float4 v[4], u[4];
#pragma unroll
        for (int i = 0; i < 4; i++) v[i] = p1[r * (HWD / 4) + i * 32];
#pragma unroll
        for (int i = 0; i < 4; i++) u[i] = p2[r * (HWD / 4) + i * 32];
#pragma unroll
        for (int i = 0; i < 4; i++) {
            part1[i] += (v[i].x + v[i].y) + (v[i].z + v[i].w);
            part2[i] += (u[i].x + u[i].y) + (u[i].z + u[i].w);
        }
    }

    // Reduce each part[i] over the 4-lane group {4g..4g+3} -> pooled col i*8+g
#pragma unroll
    for (int i = 0; i < 4; i++) {
        part1[i] += __shfl_xor_sync(0xffffffffu, part1[i], 1);
        part1[i] += __shfl_xor_sync(0xffffffffu, part1[i], 2);
        part2[i] += __shfl_xor_sync(0xffffffffu, part2[i], 1);
        part2[i] += __shfl_xor_sync(0xffffffffu, part2[i], 2);
    }

    __shared__ float sm1[8][32];
    __shared__ float sm2[8][32];
    if ((l & 3) == 0) {
        const int g = l >> 2;
#pragma unroll
        for (int i = 0; i < 4; i++) {
            sm1[w][i * 8 + g] = part1[i];
            sm2[w][i * 8 + g] = part2[i];
        }
    }
    __syncthreads();

    if (w == 0) {
        float xs = 0.f, ys = 0.f;
#pragma unroll
        for (int i = 0; i < 8; i++) { xs += sm1[i][l]; ys += sm2[i][l]; }
        // pooled values for (b, c, ph, pw=l)
        const float x = xs * (1.0f / (POOLK * POOLK));
        const float y = ys * (1.0f / (POOLK * POOLK));

        float a1 = x, a2 = y, a11 = x * x, a22 = y * y, a12 = x * y;
#pragma unroll
        for (int off = 16; off > 0; off >>= 1) {
            a1  += __shfl_down_sync(0xffffffffu, a1,  off);
            a2  += __shfl_down_sync(0xffffffffu, a2,  off);
            a11 += __shfl_down_sync(0xffffffffu, a11, off);
            a22 += __shfl_down_sync(0xffffffffu, a22, off);
            a12 += __shfl_down_sync(0xffffffffu, a12, off);
        }
        if (l == 0) {
            atomicAdd(&g_acc[c * 5 + 0], (double)a1);
            atomicAdd(&g_acc[c * 5 + 1], (double)a2);
            atomicAdd(&g_acc[c * 5 + 2], (double)a11);
            atomicAdd(&g_acc[c * 5 + 3], (double)a22);
            atomicAdd(&g_acc[c * 5 + 4], (double)a12);
        }
    }
}

__global__ __launch_bounds__(NC) void finalize_kernel(float* out) {
    const int c = threadIdx.x;
    const double n = (double)NSAMP;

    const double s1  = g_acc[c * 5 + 0];
    const double s2  = g_acc[c * 5 + 1];
    const double s11 = g_acc[c * 5 + 2];
    const double s22 = g_acc[c * 5 + 3];
    const double s12 = g_acc[c * 5 + 4];

    // Reset accumulators for the next launch / graph replay.
    g_acc[c * 5 + 0] = 0.0;
    g_acc[c * 5 + 1] = 0.0;
    g_acc[c * 5 + 2] = 0.0;
    g_acc[c * 5 + 3] = 0.0;
    g_acc[c * 5 + 4] = 0.0;

    const double m1 = s1 / n;
    const double m2 = s2 / n;
    // biased covariance (torch.mean of products of deviations)
    const double cov = s12 / n - m1 * m2;
    // unbiased std (torch.std, ddof = 1)
    const double v1 = (s11 - s1 * s1 / n) / (n - 1.0);
    const double v2 = (s22 - s2 * s2 / n) / (n - 1.0);
    const double corr = cov / (sqrt(v1) * sqrt(v2) + 1e-8);

    __shared__ double sm[NC];
    sm[c] = fabs(corr);
    __syncthreads();
    for (int s = NC / 2; s > 0; s >>= 1) {
        if (c < s) sm[c] += sm[c + s];
        __syncthreads();
    }
    if (c == 0) out[0] = (float)(1.0 - sm[0] / (double)NC);
}

extern "C" void kernel_launch(void* const* d_in, const int* in_sizes, int n_in,
                              void* d_out, int out_size) {
    const float* f1 = (const float*)d_in[0];
    const float* f2 = (const float*)d_in[1];
    float* out = (float*)d_out;

    pool_stats_kernel<<<NB * NC * PH, 256>>>(f1, f2);
    finalize_kernel<<<1, NC>>>(out);
}

// round 10
// speedup vs baseline: 1.0104x; 1.0041x over previous
#include <cuda_runtime.h>

// Problem shape (fixed by the dataset): feature1/feature2 are (8, 256, 512, 512) fp32, NCHW.
#define NB 8
#define NC 256
#define HWD 512
#define POOLK 16
#define PH (HWD / POOLK)   // 32 pooled rows
#define PW (HWD / POOLK)   // 32 pooled cols
#define NSAMP (NB * PH * PW)   // 8192 samples per channel
#define NBLOCKS (NB * NC * PH) // 65536

// Per-channel accumulators: [c*5 + {0:sx, 1:sy, 2:sxx, 3:syy, 4:sxy}]
// Statically zero-initialized; the fused finalize (last block) restores them
// to zero after reading, so every launch / graph replay sees zeros.
__device__ double g_acc[NC * 5];
__device__ unsigned int g_count;  // arrival counter, reset by last block

// One block per (b, c, ph) strip: 16 input rows x 512 cols of each feature.
// 256 threads = 8 warps; warp w owns input rows {2w, 2w+1} of the strip.
// Loads are fully warp-coalesced streaming float4s (each LDG.128 covers 4
// full 128B lines). The LAST block to finish also performs the finalize.
__global__ __launch_bounds__(256) void pool_stats_kernel(
    const float* __restrict__ f1, const float* __restrict__ f2, float* out)
{
    const int bid = blockIdx.x;
    const int ph  = bid & (PH - 1);          // 5 bits
    const int ch  = (bid >> 5) & (NC - 1);   // 8 bits
    const int b   = bid >> 13;

    const int t = threadIdx.x;
    const int w = t >> 5;   // warp 0..7
    const int l = t & 31;   // lane

    // First of the two rows this warp owns
    const long long row0 = ((long long)(b * NC + ch) * HWD + (long long)ph * POOLK + 2 * w);
    const float4* p1 = (const float4*)(f1 + row0 * HWD) + l;
    const float4* p2 = (const float4*)(f2 + row0 * HWD) + l;

    float part1[4] = {0.f, 0.f, 0.f, 0.f};
    float part2[4] = {0.f, 0.f, 0.f, 0.f};
#pragma unroll
    for (int r = 0; r < 2; r++) {
        float4 v[4], u[4];
#pragma unroll
        for (int i = 0; i < 4; i++) v[i] = __ldcs(&p1[r * (HWD / 4) + i * 32]);
#pragma unroll
        for (int i = 0; i < 4; i++) u[i] = __ldcs(&p2[r * (HWD / 4) + i * 32]);
#pragma unroll
        for (int i = 0; i < 4; i++) {
            part1[i] += (v[i].x + v[i].y) + (v[i].z + v[i].w);
            part2[i] += (u[i].x + u[i].y) + (u[i].z + u[i].w);
        }
    }

    // Reduce each part[i] over the 4-lane group {4g..4g+3} -> pooled col i*8+g
#pragma unroll
    for (int i = 0; i < 4; i++) {
        part1[i] += __shfl_xor_sync(0xffffffffu, part1[i], 1);
        part1[i] += __shfl_xor_sync(0xffffffffu, part1[i], 2);
        part2[i] += __shfl_xor_sync(0xffffffffu, part2[i], 1);
        part2[i] += __shfl_xor_sync(0xffffffffu, part2[i], 2);
    }

    __shared__ float sm1[8][32];
    __shared__ float sm2[8][32];
    if ((l & 3) == 0) {
        const int g = l >> 2;
#pragma unroll
        for (int i = 0; i < 4; i++) {
            sm1[w][i * 8 + g] = part1[i];
            sm2[w][i * 8 + g] = part2[i];
        }
    }
    __syncthreads();

    if (w == 0) {
        float xs = 0.f, ys = 0.f;
#pragma unroll
        for (int i = 0; i < 8; i++) { xs += sm1[i][l]; ys += sm2[i][l]; }
        // pooled values for (b, ch, ph, pw=l)
        const float x = xs * (1.0f / (POOLK * POOLK));
        const float y = ys * (1.0f / (POOLK * POOLK));

        float a1 = x, a2 = y, a11 = x * x, a22 = y * y, a12 = x * y;
#pragma unroll
        for (int off = 16; off > 0; off >>= 1) {
            a1  += __shfl_down_sync(0xffffffffu, a1,  off);
            a2  += __shfl_down_sync(0xffffffffu, a2,  off);
            a11 += __shfl_down_sync(0xffffffffu, a11, off);
            a22 += __shfl_down_sync(0xffffffffu, a22, off);
            a12 += __shfl_down_sync(0xffffffffu, a12, off);
        }
        if (l == 0) {
            atomicAdd(&g_acc[ch * 5 + 0], (double)a1);
            atomicAdd(&g_acc[ch * 5 + 1], (double)a2);
            atomicAdd(&g_acc[ch * 5 + 2], (double)a11);
            atomicAdd(&g_acc[ch * 5 + 3], (double)a22);
            atomicAdd(&g_acc[ch * 5 + 4], (double)a12);
        }
    }

    // ---- last-block detection ----
    __shared__ bool is_last;
    if (t == 0) {
        __threadfence();  // make this block's g_acc atomics visible before counting
        unsigned int old = atomicAdd(&g_count, 1u);
        is_last = (old == (unsigned int)(NBLOCKS - 1));
    }
    __syncthreads();
    if (!is_last) return;

    // ---- fused finalize: thread t owns channel t ----
    const int c = t;
    const double n = (double)NSAMP;

    const double s1  = __ldcg(&g_acc[c * 5 + 0]);
    const double s2  = __ldcg(&g_acc[c * 5 + 1]);
    const double s11 = __ldcg(&g_acc[c * 5 + 2]);
    const double s22 = __ldcg(&g_acc[c * 5 + 3]);
    const double s12 = __ldcg(&g_acc[c * 5 + 4]);

    // Reset state for the next launch / graph replay.
    g_acc[c * 5 + 0] = 0.0;
    g_acc[c * 5 + 1] = 0.0;
    g_acc[c * 5 + 2] = 0.0;
    g_acc[c * 5 + 3] = 0.0;
    g_acc[c * 5 + 4] = 0.0;
    if (t == 0) g_count = 0u;

    const double m1 = s1 / n;
    const double m2 = s2 / n;
    // biased covariance (torch.mean of products of deviations)
    const double cov = s12 / n - m1 * m2;
    // unbiased std (torch.std, ddof = 1)
    const double v1 = (s11 - s1 * s1 / n) / (n - 1.0);
    const double v2 = (s22 - s2 * s2 / n) / (n - 1.0);
    const double corr = cov / (sqrt(v1) * sqrt(v2) + 1e-8);

    // block reduction of |corr| over 256 channels
    double ac = fabs(corr);
#pragma unroll
    for (int off = 16; off > 0; off >>= 1)
        ac += __shfl_down_sync(0xffffffffu, ac, off);

    __shared__ double smd[8];
    if (l == 0) smd[w] = ac;
    __syncthreads();
    if (t == 0) {
        double tot = 0.0;
#pragma unroll
        for (int i = 0; i < 8; i++) tot += smd[i];
        out[0] = (float)(1.0 - tot / (double)NC);
    }
}

extern "C" void kernel_launch(void* const* d_in, const int* in_sizes, int n_in,
                              void* d_out, int out_size) {
    const float* f1 = (const float*)d_in[0];
    const float* f2 = (const float*)d_in[1];
    float* out = (float*)d_out;

    pool_stats_kernel<<<NBLOCKS, 256>>>(f1, f2, out);
}

// round 11
// speedup vs baseline: 1.0105x; 1.0001x over previous
#include <cuda_runtime.h>

// Problem shape (fixed by the dataset): feature1/feature2 are (8, 256, 512, 512) fp32, NCHW.
#define NB 8
#define NC 256
#define HWD 512
#define POOLK 16
#define PH (HWD / POOLK)   // 32 pooled rows
#define PW (HWD / POOLK)   // 32 pooled cols
#define NSAMP (NB * PH * PW)   // 8192 samples per channel
#define NBLOCKS (NB * NC * PH) // 65536

// Per-channel accumulators: [c*5 + {0:sx, 1:sy, 2:sxx, 3:syy, 4:sxy}]
// Statically zero-initialized; the fused finalize (last block) restores them
// to zero after reading, so every launch / graph replay sees zeros.
__device__ double g_acc[NC * 5];
__device__ unsigned int g_count;  // arrival counter, reset by last block

// One block per (b, c, ph) strip: 16 input rows x 512 cols of each feature.
// 256 threads = 8 warps; warp w owns input rows {2w, 2w+1} of the strip.
// Loads are fully warp-coalesced streaming float4s (each LDG.128 covers 4
// full 128B lines). The LAST block to finish also performs the finalize.
__global__ __launch_bounds__(256) void pool_stats_kernel(
    const float* __restrict__ f1, const float* __restrict__ f2, float* out)
{
    const int bid = blockIdx.x;
    const int ph  = bid & (PH - 1);          // 5 bits
    const int ch  = (bid >> 5) & (NC - 1);   // 8 bits
    const int b   = bid >> 13;

    const int t = threadIdx.x;
    const int w = t >> 5;   // warp 0..7
    const int l = t & 31;   // lane

    // First of the two rows this warp owns
    const long long row0 = ((long long)(b * NC + ch) * HWD + (long long)ph * POOLK + 2 * w);
    const float4* p1 = (const float4*)(f1 + row0 * HWD) + l;
    const float4* p2 = (const float4*)(f2 + row0 * HWD) + l;

    float part1[4] = {0.f, 0.f, 0.f, 0.f};
    float part2[4] = {0.f, 0.f, 0.f, 0.f};
#pragma unroll
    for (int r = 0; r < 2; r++) {
        float4 v[4], u[4];
#pragma unroll
        for (int i = 0; i < 4; i++) v[i] = __ldcs(&p1[r * (HWD / 4) + i * 32]);
#pragma unroll
        for (int i = 0; i < 4; i++) u[i] = __ldcs(&p2[r * (HWD / 4) + i * 32]);
#pragma unroll
        for (int i = 0; i < 4; i++) {
            part1[i] += (v[i].x + v[i].y) + (v[i].z + v[i].w);
            part2[i] += (u[i].x + u[i].y) + (u[i].z + u[i].w);
        }
    }

    // Reduce each part[i] over the 4-lane group {4g..4g+3} -> pooled col i*8+g
#pragma unroll
    for (int i = 0; i < 4; i++) {
        part1[i] += __shfl_xor_sync(0xffffffffu, part1[i], 1);
        part1[i] += __shfl_xor_sync(0xffffffffu, part1[i], 2);
        part2[i] += __shfl_xor_sync(0xffffffffu, part2[i], 1);
        part2[i] += __shfl_xor_sync(0xffffffffu, part2[i], 2);
    }

    __shared__ float sm1[8][32];
    __shared__ float sm2[8][32];
    if ((l & 3) == 0) {
        const int g = l >> 2;
#pragma unroll
        for (int i = 0; i < 4; i++) {
            sm1[w][i * 8 + g] = part1[i];
            sm2[w][i * 8 + g] = part2[i];
        }
    }
    __syncthreads();

    if (w == 0) {
        float xs = 0.f, ys = 0.f;
#pragma unroll
        for (int i = 0; i < 8; i++) { xs += sm1[i][l]; ys += sm2[i][l]; }
        // pooled values for (b, ch, ph, pw=l)
        const float x = xs * (1.0f / (POOLK * POOLK));
        const float y = ys * (1.0f / (POOLK * POOLK));

        float a1 = x, a2 = y, a11 = x * x, a22 = y * y, a12 = x * y;
#pragma unroll
        for (int off = 16; off > 0; off >>= 1) {
            a1  += __shfl_down_sync(0xffffffffu, a1,  off);
            a2  += __shfl_down_sync(0xffffffffu, a2,  off);
            a11 += __shfl_down_sync(0xffffffffu, a11, off);
            a22 += __shfl_down_sync(0xffffffffu, a22, off);
            a12 += __shfl_down_sync(0xffffffffu, a12, off);
        }
        if (l == 0) {
            atomicAdd(&g_acc[ch * 5 + 0], (double)a1);
            atomicAdd(&g_acc[ch * 5 + 1], (double)a2);
            atomicAdd(&g_acc[ch * 5 + 2], (double)a11);
            atomicAdd(&g_acc[ch * 5 + 3], (double)a22);
            atomicAdd(&g_acc[ch * 5 + 4], (double)a12);
        }
    }

    // ---- last-block detection ----
    __shared__ bool is_last;
    if (t == 0) {
        __threadfence();  // make this block's g_acc atomics visible before counting
        unsigned int old = atomicAdd(&g_count, 1u);
        is_last = (old == (unsigned int)(NBLOCKS - 1));
    }
    __syncthreads();
    if (!is_last) return;

    // ---- fused finalize: thread t owns channel t ----
    const int c = t;
    const double n = (double)NSAMP;

    const double s1  = __ldcg(&g_acc[c * 5 + 0]);
    const double s2  = __ldcg(&g_acc[c * 5 + 1]);
    const double s11 = __ldcg(&g_acc[c * 5 + 2]);
    const double s22 = __ldcg(&g_acc[c * 5 + 3]);
    const double s12 = __ldcg(&g_acc[c * 5 + 4]);

    // Reset state for the next launch / graph replay.
    g_acc[c * 5 + 0] = 0.0;
    g_acc[c * 5 + 1] = 0.0;
    g_acc[c * 5 + 2] = 0.0;
    g_acc[c * 5 + 3] = 0.0;
    g_acc[c * 5 + 4] = 0.0;
    if (t == 0) g_count = 0u;

    const double m1 = s1 / n;
    const double m2 = s2 / n;
    // biased covariance (torch.mean of products of deviations)
    const double cov = s12 / n - m1 * m2;
    // unbiased std (torch.std, ddof = 1)
    const double v1 = (s11 - s1 * s1 / n) / (n - 1.0);
    const double v2 = (s22 - s2 * s2 / n) / (n - 1.0);
    const double corr = cov / (sqrt(v1) * sqrt(v2) + 1e-8);

    // block reduction of |corr| over 256 channels
    double ac = fabs(corr);
#pragma unroll
    for (int off = 16; off > 0; off >>= 1)
        ac += __shfl_down_sync(0xffffffffu, ac, off);

    __shared__ double smd[8];
    if (l == 0) smd[w] = ac;
    __syncthreads();
    if (t == 0) {
        double tot = 0.0;
#pragma unroll
        for (int i = 0; i < 8; i++) tot += smd[i];
        out[0] = (float)(1.0 - tot / (double)NC);
    }
}

extern "C" void kernel_launch(void* const* d_in, const int* in_sizes, int n_in,
                              void* d_out, int out_size) {
    const float* f1 = (const float*)d_in[0];
    const float* f2 = (const float*)d_in[1];
    float* out = (float*)d_out;

    pool_stats_kernel<<<NBLOCKS, 256>>>(f1, f2, out);
}